// round 5
// baseline (speedup 1.0000x reference)
#include <cuda_runtime.h>
#include <cstdint>

// Dual COO SpMM:  out[r, 0:256]   += val1[e] * x[col1[e], :]  for row1[e]==r
//                 out[r, 256:512] += val2[e] * x[col2[e], :]
// x: [N, 256] f32.  out: [N, 512] f32.
//
// Warp-per-edge. Each of the 32 lanes handles 2 float4 column chunks
// (lane, lane+32) -> full 256-float row per warp. Scatter via
// red.global.add.v4.f32 (no-return vector reduction). x (20MB) fits in L2,
// so gathers should be L2 hits -> L2-throughput bound.

#define BLOCK 256
#define WARPS_PER_BLOCK (BLOCK / 32)

__global__ __launch_bounds__(BLOCK)
void hetconv_spmm_atomic(const float4* __restrict__ x4,
                         const int*   __restrict__ row1,
                         const int*   __restrict__ col1,
                         const float* __restrict__ val1,
                         const int*   __restrict__ row2,
                         const int*   __restrict__ col2,
                         const float* __restrict__ val2,
                         float* __restrict__ out,
                         int E)
{
    int lane = threadIdx.x & 31;
    long long warp_gid = ((long long)blockIdx.x * WARPS_PER_BLOCK) + (threadIdx.x >> 5);
    if (warp_gid >= 2LL * E) return;

    int r, c, base;
    float v;
    if (warp_gid < E) {
        int ei = (int)warp_gid;
        r = __ldg(&row1[ei]); c = __ldg(&col1[ei]); v = __ldg(&val1[ei]); base = 0;
    } else {
        int ei = (int)(warp_gid - E);
        r = __ldg(&row2[ei]); c = __ldg(&col2[ei]); v = __ldg(&val2[ei]); base = 64;
    }

    const float4* xp = x4 + (size_t)c * 64 + lane;
    float4 a = __ldg(xp);        // chunk [lane]
    float4 b = __ldg(xp + 32);   // chunk [lane+32]  (independent -> MLP=2)

    float4 ma, mb;
    ma.x = v * a.x; ma.y = v * a.y; ma.z = v * a.z; ma.w = v * a.w;
    mb.x = v * b.x; mb.y = v * b.y; mb.z = v * b.z; mb.w = v * b.w;

    float* p = out + (size_t)r * 512 + (size_t)(base + lane) * 4;
    asm volatile("red.global.add.v4.f32 [%0], {%1, %2, %3, %4};"
                 :: "l"(p), "f"(ma.x), "f"(ma.y), "f"(ma.z), "f"(ma.w)
                 : "memory");
    asm volatile("red.global.add.v4.f32 [%0], {%1, %2, %3, %4};"
                 :: "l"(p + 128), "f"(mb.x), "f"(mb.y), "f"(mb.z), "f"(mb.w)
                 : "memory");
}

extern "C" void kernel_launch(void* const* d_in, const int* in_sizes, int n_in,
                              void* d_out, int out_size)
{
    const float* x    = (const float*)d_in[0];
    const int*   row1 = (const int*)  d_in[1];
    const int*   col1 = (const int*)  d_in[2];
    const float* val1 = (const float*)d_in[3];
    const int*   row2 = (const int*)  d_in[4];
    const int*   col2 = (const int*)  d_in[5];
    const float* val2 = (const float*)d_in[6];
    float* out = (float*)d_out;

    int E = in_sizes[1];   // edges per adjacency

    // Output is poisoned 0xAA by the harness; we accumulate, so zero it first.
    cudaMemsetAsync(d_out, 0, (size_t)out_size * sizeof(float));

    long long total_warps = 2LL * E;
    int blocks = (int)((total_warps + WARPS_PER_BLOCK - 1) / WARPS_PER_BLOCK);
    hetconv_spmm_atomic<<<blocks, BLOCK>>>(
        (const float4*)x, row1, col1, val1, row2, col2, val2, out, E);
}